// round 1
// baseline (speedup 1.0000x reference)
#include <cuda_runtime.h>
#include <cuda_bf16.h>
#include <math.h>

// Problem constants (fixed by the reference)
#define BB   4
#define TT   2048
#define MM   16
#define DD   512
#define HH   8
#define DFF  2048
#define WIN  128
#define LL   (MM + TT)          // 2064
#define NROWS (BB * LL)         // 8256
#define DH   64

// ---------------------------------------------------------------------------
// Scratch (static device arrays; allocation-free per harness rules)
// ---------------------------------------------------------------------------
__device__ float g_x2  [(size_t)NROWS * DD];    // LN1 output
__device__ float g_qkv [(size_t)NROWS * 3 * DD];// qkv
__device__ float g_attn[(size_t)NROWS * DD];    // attention output (pre out-proj)
__device__ float g_xres[(size_t)NROWS * DD];    // x + attn_out
__device__ float g_hln [(size_t)NROWS * DD];    // LN2 output
__device__ float g_ffn [(size_t)NROWS * DFF];   // gelu(h@w1^T+b1)

// ---------------------------------------------------------------------------
// LayerNorm over D=512. One block (128 threads) per row; float4 loads.
// ---------------------------------------------------------------------------
__global__ void ln_kernel(const float* __restrict__ x,
                          const float* __restrict__ g,
                          const float* __restrict__ b,
                          float* __restrict__ y)
{
    int row = blockIdx.x;
    int t = threadIdx.x;          // 0..127
    const float4* xr = (const float4*)(x + (size_t)row * DD);
    float4 v = xr[t];
    float s  = v.x + v.y + v.z + v.w;
    float ss = v.x*v.x + v.y*v.y + v.z*v.z + v.w*v.w;

    int lane = t & 31, wid = t >> 5;
    #pragma unroll
    for (int o = 16; o > 0; o >>= 1) {
        s  += __shfl_xor_sync(0xffffffffu, s,  o);
        ss += __shfl_xor_sync(0xffffffffu, ss, o);
    }
    __shared__ float sh[8];
    if (lane == 0) { sh[wid] = s; sh[wid + 4] = ss; }
    __syncthreads();
    s  = sh[0] + sh[1] + sh[2] + sh[3];
    ss = sh[4] + sh[5] + sh[6] + sh[7];

    float mu  = s * (1.0f / DD);
    float var = ss * (1.0f / DD) - mu * mu;
    float inv = rsqrtf(var + 1e-5f);

    float4 gg = ((const float4*)g)[t];
    float4 bb = ((const float4*)b)[t];
    float4 o4;
    o4.x = (v.x - mu) * inv * gg.x + bb.x;
    o4.y = (v.y - mu) * inv * gg.y + bb.y;
    o4.z = (v.z - mu) * inv * gg.z + bb.z;
    o4.w = (v.w - mu) * inv * gg.w + bb.w;
    ((float4*)(y + (size_t)row * DD))[t] = o4;
}

// ---------------------------------------------------------------------------
// GEMM: C[N,Mo] = A[N,K] @ W[Mo,K]^T + bias (+res) (+gelu)
// 64x64 tile, 256 threads, each computes 4x4. BK=16.
// ACT: 0 = none, 1 = exact gelu
// ---------------------------------------------------------------------------
template<int ACT>
__global__ void gemm_kernel(const float* __restrict__ A,
                            const float* __restrict__ W,
                            const float* __restrict__ bias,
                            const float* __restrict__ res,
                            float* __restrict__ C,
                            int N, int Mo, int K)
{
    __shared__ __align__(16) float As[16][68];
    __shared__ __align__(16) float Ws[16][68];

    int t  = threadIdx.x;            // 0..255
    int tx = t & 15;                 // col group
    int ty = t >> 4;                 // row group
    int n0 = blockIdx.y * 64;
    int m0 = blockIdx.x * 64;

    int lrow = t >> 2;               // 0..63
    int lk4  = (t & 3) * 4;          // 0,4,8,12
    const float* Aptr = A + (size_t)(n0 + lrow) * K + lk4;
    const float* Wptr = W + (size_t)(m0 + lrow) * K + lk4;

    float acc[4][4];
    #pragma unroll
    for (int i = 0; i < 4; i++)
        #pragma unroll
        for (int j = 0; j < 4; j++) acc[i][j] = 0.0f;

    for (int k0 = 0; k0 < K; k0 += 16) {
        float4 av = *(const float4*)(Aptr + k0);
        float4 wv = *(const float4*)(Wptr + k0);
        As[lk4 + 0][lrow] = av.x; As[lk4 + 1][lrow] = av.y;
        As[lk4 + 2][lrow] = av.z; As[lk4 + 3][lrow] = av.w;
        Ws[lk4 + 0][lrow] = wv.x; Ws[lk4 + 1][lrow] = wv.y;
        Ws[lk4 + 2][lrow] = wv.z; Ws[lk4 + 3][lrow] = wv.w;
        __syncthreads();

        #pragma unroll
        for (int kk = 0; kk < 16; kk++) {
            float4 a4 = *(const float4*)&As[kk][ty * 4];
            float4 w4 = *(const float4*)&Ws[kk][tx * 4];
            acc[0][0] += a4.x * w4.x; acc[0][1] += a4.x * w4.y;
            acc[0][2] += a4.x * w4.z; acc[0][3] += a4.x * w4.w;
            acc[1][0] += a4.y * w4.x; acc[1][1] += a4.y * w4.y;
            acc[1][2] += a4.y * w4.z; acc[1][3] += a4.y * w4.w;
            acc[2][0] += a4.z * w4.x; acc[2][1] += a4.z * w4.y;
            acc[2][2] += a4.z * w4.z; acc[2][3] += a4.z * w4.w;
            acc[3][0] += a4.w * w4.x; acc[3][1] += a4.w * w4.y;
            acc[3][2] += a4.w * w4.z; acc[3][3] += a4.w * w4.w;
        }
        __syncthreads();
    }

    #pragma unroll
    for (int i = 0; i < 4; i++) {
        int row = n0 + ty * 4 + i;
        #pragma unroll
        for (int j = 0; j < 4; j++) {
            int col = m0 + tx * 4 + j;
            float v = acc[i][j] + bias[col];
            if (ACT == 1) {
                v = 0.5f * v * (1.0f + erff(v * 0.70710678118654752f));
            }
            if (res) v += res[(size_t)row * Mo + col];
            C[(size_t)row * Mo + col] = v;
        }
    }
}

// ---------------------------------------------------------------------------
// Banded attention. One warp per (b,h,query). Online softmax over
// allowed keys: mem-causal for i<M; [0,M) + sliding window for i>=M.
// qkv layout: [(b*L + l) * 1536 + {0,512,1024} + h*64 + d]
// ---------------------------------------------------------------------------
__global__ void attn_kernel(const float* __restrict__ qkv,
                            float* __restrict__ out)
{
    int lane = threadIdx.x & 31;
    int wid  = threadIdx.x >> 5;          // 0..7
    int bh = blockIdx.x;                  // 0..B*H-1
    int b = bh >> 3;                      // /H
    int h = bh & 7;                       // %H
    int i = blockIdx.y * 8 + wid;
    if (i >= LL) return;

    const float* base = qkv + (size_t)b * LL * (3 * DD);
    const float* qrow = base + (size_t)i * (3 * DD) + h * DH;
    float q0 = qrow[lane];
    float q1 = qrow[lane + 32];

    float m = -1e30f, dsum = 0.0f, a0 = 0.0f, a1 = 0.0f;
    const float scale = 0.125f;           // 1/sqrt(64)

    // key ranges
    int rA_lo, rA_hi, rB_lo, rB_hi;       // inclusive [lo, hi]
    if (i < MM) {
        rA_lo = 0; rA_hi = i;
        rB_lo = 1; rB_hi = 0;             // empty
    } else {
        rA_lo = 0; rA_hi = MM - 1;
        rB_lo = (i - WIN + 1 > MM) ? (i - WIN + 1) : MM;
        rB_hi = i;
    }

    for (int r = 0; r < 2; r++) {
        int lo = (r == 0) ? rA_lo : rB_lo;
        int hi = (r == 0) ? rA_hi : rB_hi;
        for (int j = lo; j <= hi; j++) {
            const float* krow = base + (size_t)j * (3 * DD) + DD + h * DH;
            float s = q0 * krow[lane] + q1 * krow[lane + 32];
            #pragma unroll
            for (int o = 16; o > 0; o >>= 1)
                s += __shfl_xor_sync(0xffffffffu, s, o);
            s *= scale;
            float mnew = fmaxf(m, s);
            float c = __expf(m - mnew);
            float p = __expf(s - mnew);
            const float* vrow = krow + DD;
            dsum = dsum * c + p;
            a0 = a0 * c + p * vrow[lane];
            a1 = a1 * c + p * vrow[lane + 32];
            m = mnew;
        }
    }

    float inv = 1.0f / dsum;
    float* orow = out + ((size_t)(b * LL + i)) * DD + h * DH;
    orow[lane]      = a0 * inv;
    orow[lane + 32] = a1 * inv;
}

// ---------------------------------------------------------------------------
// Launch
// ---------------------------------------------------------------------------
extern "C" void kernel_launch(void* const* d_in, const int* in_sizes, int n_in,
                              void* d_out, int out_size)
{
    const float* x     = (const float*)d_in[0];
    const float* in_w  = (const float*)d_in[1];
    const float* in_b  = (const float*)d_in[2];
    const float* out_w = (const float*)d_in[3];
    const float* out_b = (const float*)d_in[4];
    const float* ln1g  = (const float*)d_in[5];
    const float* ln1b  = (const float*)d_in[6];
    const float* ln2g  = (const float*)d_in[7];
    const float* ln2b  = (const float*)d_in[8];
    const float* w1    = (const float*)d_in[9];
    const float* b1    = (const float*)d_in[10];
    const float* w2    = (const float*)d_in[11];
    const float* b2    = (const float*)d_in[12];
    float* out = (float*)d_out;

    float *x2, *qkv, *attn, *xres, *hln, *ffn;
    cudaGetSymbolAddress((void**)&x2,   g_x2);
    cudaGetSymbolAddress((void**)&qkv,  g_qkv);
    cudaGetSymbolAddress((void**)&attn, g_attn);
    cudaGetSymbolAddress((void**)&xres, g_xres);
    cudaGetSymbolAddress((void**)&hln,  g_hln);
    cudaGetSymbolAddress((void**)&ffn,  g_ffn);

    // 1. LN1
    ln_kernel<<<NROWS, 128>>>(x, ln1g, ln1b, x2);
    // 2. QKV = x2 @ in_w^T + in_b   (8256 x 1536 x 512)
    gemm_kernel<0><<<dim3((3 * DD) / 64, NROWS / 64), 256>>>(
        x2, in_w, in_b, nullptr, qkv, NROWS, 3 * DD, DD);
    // 3. attention
    attn_kernel<<<dim3(BB * HH, LL / 8), 256>>>(qkv, attn);
    // 4. xres = attn @ out_w^T + out_b + x   (8256 x 512 x 512)
    gemm_kernel<0><<<dim3(DD / 64, NROWS / 64), 256>>>(
        attn, out_w, out_b, x, xres, NROWS, DD, DD);
    // 5. LN2
    ln_kernel<<<NROWS, 128>>>(xres, ln2g, ln2b, hln);
    // 6. ffn = gelu(hln @ w1^T + b1)   (8256 x 2048 x 512)
    gemm_kernel<1><<<dim3(DFF / 64, NROWS / 64), 256>>>(
        hln, w1, b1, nullptr, ffn, NROWS, DFF, DD);
    // 7. out = ffn @ w2^T + b2 + xres   (8256 x 512 x 2048)
    gemm_kernel<0><<<dim3(DD / 64, NROWS / 64), 256>>>(
        ffn, w2, b2, xres, out, NROWS, DD, DFF);
}

// round 3
// speedup vs baseline: 1.9487x; 1.9487x over previous
#include <cuda_runtime.h>
#include <cuda_bf16.h>
#include <math.h>

// Problem constants (fixed by the reference)
#define BB   4
#define TT   2048
#define MM   16
#define DD   512
#define HH   8
#define DFF  2048
#define WIN  128
#define LL   (MM + TT)          // 2064
#define NROWS (BB * LL)         // 8256
#define DH   64

// ---------------------------------------------------------------------------
// Scratch
// ---------------------------------------------------------------------------
__device__ float g_x2  [(size_t)NROWS * DD];
__device__ float g_qkv [(size_t)NROWS * 3 * DD];
__device__ float g_attn[(size_t)NROWS * DD];
__device__ float g_xres[(size_t)NROWS * DD];
__device__ float g_hln [(size_t)NROWS * DD];
__device__ float g_ffn [(size_t)NROWS * DFF];

// ---------------------------------------------------------------------------
// LayerNorm over D=512. One block (128 threads) per row.
// ---------------------------------------------------------------------------
__global__ void ln_kernel(const float* __restrict__ x,
                          const float* __restrict__ g,
                          const float* __restrict__ b,
                          float* __restrict__ y)
{
    int row = blockIdx.x;
    int t = threadIdx.x;
    const float4* xr = (const float4*)(x + (size_t)row * DD);
    float4 v = xr[t];
    float s  = v.x + v.y + v.z + v.w;
    float ss = v.x*v.x + v.y*v.y + v.z*v.z + v.w*v.w;

    int lane = t & 31, wid = t >> 5;
    #pragma unroll
    for (int o = 16; o > 0; o >>= 1) {
        s  += __shfl_xor_sync(0xffffffffu, s,  o);
        ss += __shfl_xor_sync(0xffffffffu, ss, o);
    }
    __shared__ float sh[8];
    if (lane == 0) { sh[wid] = s; sh[wid + 4] = ss; }
    __syncthreads();
    s  = sh[0] + sh[1] + sh[2] + sh[3];
    ss = sh[4] + sh[5] + sh[6] + sh[7];

    float mu  = s * (1.0f / DD);
    float var = ss * (1.0f / DD) - mu * mu;
    float inv = rsqrtf(var + 1e-5f);

    float4 gg = ((const float4*)g)[t];
    float4 bb = ((const float4*)b)[t];
    float4 o4;
    o4.x = (v.x - mu) * inv * gg.x + bb.x;
    o4.y = (v.y - mu) * inv * gg.y + bb.y;
    o4.z = (v.z - mu) * inv * gg.z + bb.z;
    o4.w = (v.w - mu) * inv * gg.w + bb.w;
    ((float4*)(y + (size_t)row * DD))[t] = o4;
}

// ---------------------------------------------------------------------------
// TF32 tensor-core GEMM: C[N,Mo] = A[N,K] @ W[Mo,K]^T + bias (+res) (+gelu)
// Block tile 128(N) x 128(Mo), BK=16, 256 threads (8 warps, 2x4 warp grid,
// warp tile 64x32), mma.sync.m16n8k8 tf32, double-buffered smem (stride 20).
// ---------------------------------------------------------------------------
__device__ __forceinline__ float to_tf32(float x) {
    unsigned y;
    asm("cvt.rna.tf32.f32 %0, %1;" : "=r"(y) : "f"(x));
    return __uint_as_float(y);
}

__device__ __forceinline__ void mma_tf32(float* c, const unsigned* a, const unsigned* b) {
    asm volatile(
        "mma.sync.aligned.m16n8k8.row.col.f32.tf32.tf32.f32 "
        "{%0,%1,%2,%3}, {%4,%5,%6,%7}, {%8,%9}, {%0,%1,%2,%3};"
        : "+f"(c[0]), "+f"(c[1]), "+f"(c[2]), "+f"(c[3])
        : "r"(a[0]), "r"(a[1]), "r"(a[2]), "r"(a[3]), "r"(b[0]), "r"(b[1]));
}

template<int ACT>
__global__ __launch_bounds__(256) void mma_gemm(
    const float* __restrict__ A,
    const float* __restrict__ W,
    const float* __restrict__ bias,
    const float* __restrict__ res,
    float* __restrict__ C,
    int N, int Mo, int K)
{
    __shared__ __align__(16) float As[2][128][20];
    __shared__ __align__(16) float Ws[2][128][20];

    int tid  = threadIdx.x;
    int lane = tid & 31;
    int wid  = tid >> 5;
    int wm   = wid >> 2;          // 0..1
    int wn   = wid & 3;           // 0..3
    int n0   = blockIdx.y * 128;  // row block (N)
    int m0   = blockIdx.x * 128;  // col block (Mo)

    int lr = tid >> 2;            // 0..63
    int lc = (tid & 3) * 4;       // 0,4,8,12

    const float* Ap0 = A + (size_t)(n0 + lr)      * K + lc;
    const float* Ap1 = A + (size_t)(n0 + lr + 64) * K + lc;
    const float* Wp0 = W + (size_t)(m0 + lr)      * K + lc;
    const float* Wp1 = W + (size_t)(m0 + lr + 64) * K + lc;
    bool v0 = (n0 + lr)      < N;
    bool v1 = (n0 + lr + 64) < N;

    float4 ra0, ra1, rw0, rw1;
    const float4 z4 = make_float4(0.f, 0.f, 0.f, 0.f);

    float acc[4][4][4];
    #pragma unroll
    for (int i = 0; i < 4; i++)
        #pragma unroll
        for (int j = 0; j < 4; j++)
            #pragma unroll
            for (int q = 0; q < 4; q++) acc[i][j][q] = 0.0f;

    int nIter = K >> 4;

    // prologue: load tile 0, store to buffer 0
    ra0 = v0 ? *(const float4*)Ap0 : z4;
    ra1 = v1 ? *(const float4*)Ap1 : z4;
    rw0 = *(const float4*)Wp0;
    rw1 = *(const float4*)Wp1;
    {
        float4* d;
        d = (float4*)&As[0][lr][lc];
        *d = make_float4(to_tf32(ra0.x), to_tf32(ra0.y), to_tf32(ra0.z), to_tf32(ra0.w));
        d = (float4*)&As[0][lr + 64][lc];
        *d = make_float4(to_tf32(ra1.x), to_tf32(ra1.y), to_tf32(ra1.z), to_tf32(ra1.w));
        d = (float4*)&Ws[0][lr][lc];
        *d = make_float4(to_tf32(rw0.x), to_tf32(rw0.y), to_tf32(rw0.z), to_tf32(rw0.w));
        d = (float4*)&Ws[0][lr + 64][lc];
        *d = make_float4(to_tf32(rw1.x), to_tf32(rw1.y), to_tf32(rw1.z), to_tf32(rw1.w));
    }
    __syncthreads();

    int buf = 0;
    for (int it = 0; it < nIter; it++) {
        // prefetch next tile from global into registers
        if (it + 1 < nIter) {
            int k0 = (it + 1) << 4;
            ra0 = v0 ? *(const float4*)(Ap0 + k0) : z4;
            ra1 = v1 ? *(const float4*)(Ap1 + k0) : z4;
            rw0 = *(const float4*)(Wp0 + k0);
            rw1 = *(const float4*)(Wp1 + k0);
        }

        // compute on current buffer
        #pragma unroll
        for (int ks = 0; ks < 2; ks++) {
            int kb = ks * 8;
            unsigned af[4][4];
            unsigned bf[4][2];
            int lq = lane >> 2;      // 0..7
            int lk = lane & 3;       // 0..3
            #pragma unroll
            for (int am = 0; am < 4; am++) {
                int mr = wm * 64 + am * 16 + lq;
                af[am][0] = __float_as_uint(As[buf][mr][kb + lk]);
                af[am][1] = __float_as_uint(As[buf][mr + 8][kb + lk]);
                af[am][2] = __float_as_uint(As[buf][mr][kb + lk + 4]);
                af[am][3] = __float_as_uint(As[buf][mr + 8][kb + lk + 4]);
            }
            #pragma unroll
            for (int an = 0; an < 4; an++) {
                int nr = wn * 32 + an * 8 + lq;
                bf[an][0] = __float_as_uint(Ws[buf][nr][kb + lk]);
                bf[an][1] = __float_as_uint(Ws[buf][nr][kb + lk + 4]);
            }
            #pragma unroll
            for (int am = 0; am < 4; am++)
                #pragma unroll
                for (int an = 0; an < 4; an++)
                    mma_tf32(acc[am][an], af[am], bf[an]);
        }

        // store prefetched tile into the other buffer
        if (it + 1 < nIter) {
            int nb = buf ^ 1;
            float4* d;
            d = (float4*)&As[nb][lr][lc];
            *d = make_float4(to_tf32(ra0.x), to_tf32(ra0.y), to_tf32(ra0.z), to_tf32(ra0.w));
            d = (float4*)&As[nb][lr + 64][lc];
            *d = make_float4(to_tf32(ra1.x), to_tf32(ra1.y), to_tf32(ra1.z), to_tf32(ra1.w));
            d = (float4*)&Ws[nb][lr][lc];
            *d = make_float4(to_tf32(rw0.x), to_tf32(rw0.y), to_tf32(rw0.z), to_tf32(rw0.w));
            d = (float4*)&Ws[nb][lr + 64][lc];
            *d = make_float4(to_tf32(rw1.x), to_tf32(rw1.y), to_tf32(rw1.z), to_tf32(rw1.w));
        }
        __syncthreads();
        buf ^= 1;
    }

    // epilogue
    int lq = lane >> 2;
    int lk = lane & 3;
    #pragma unroll
    for (int am = 0; am < 4; am++) {
        #pragma unroll
        for (int an = 0; an < 4; an++) {
            int r0 = n0 + wm * 64 + am * 16 + lq;
            int c0 = m0 + wn * 32 + an * 8 + lk * 2;
            float b0 = bias[c0], b1 = bias[c0 + 1];
            #pragma unroll
            for (int half = 0; half < 2; half++) {
                int row = r0 + half * 8;
                if (row < N) {
                    float u0 = acc[am][an][half * 2 + 0] + b0;
                    float u1 = acc[am][an][half * 2 + 1] + b1;
                    if (ACT == 1) {
                        u0 = 0.5f * u0 * (1.0f + erff(u0 * 0.70710678118654752f));
                        u1 = 0.5f * u1 * (1.0f + erff(u1 * 0.70710678118654752f));
                    }
                    if (res) {
                        const float2 rr = *(const float2*)(res + (size_t)row * Mo + c0);
                        u0 += rr.x; u1 += rr.y;
                    }
                    *(float2*)(C + (size_t)row * Mo + c0) = make_float2(u0, u1);
                }
            }
        }
    }
}

// ---------------------------------------------------------------------------
// Banded attention. One warp per (b,h,query). Online softmax.
// ---------------------------------------------------------------------------
__global__ void attn_kernel(const float* __restrict__ qkv,
                            float* __restrict__ out)
{
    int lane = threadIdx.x & 31;
    int wid  = threadIdx.x >> 5;
    int bh = blockIdx.x;
    int b = bh >> 3;
    int h = bh & 7;
    int i = blockIdx.y * 8 + wid;
    if (i >= LL) return;

    const float* base = qkv + (size_t)b * LL * (3 * DD);
    const float* qrow = base + (size_t)i * (3 * DD) + h * DH;
    float q0 = qrow[lane];
    float q1 = qrow[lane + 32];

    float m = -1e30f, dsum = 0.0f, a0 = 0.0f, a1 = 0.0f;
    const float scale = 0.125f;

    int rA_lo, rA_hi, rB_lo, rB_hi;
    if (i < MM) {
        rA_lo = 0; rA_hi = i;
        rB_lo = 1; rB_hi = 0;
    } else {
        rA_lo = 0; rA_hi = MM - 1;
        rB_lo = (i - WIN + 1 > MM) ? (i - WIN + 1) : MM;
        rB_hi = i;
    }

    for (int r = 0; r < 2; r++) {
        int lo = (r == 0) ? rA_lo : rB_lo;
        int hi = (r == 0) ? rA_hi : rB_hi;
        for (int j = lo; j <= hi; j++) {
            const float* krow = base + (size_t)j * (3 * DD) + DD + h * DH;
            float s = q0 * krow[lane] + q1 * krow[lane + 32];
            #pragma unroll
            for (int o = 16; o > 0; o >>= 1)
                s += __shfl_xor_sync(0xffffffffu, s, o);
            s *= scale;
            float mnew = fmaxf(m, s);
            float c = __expf(m - mnew);
            float p = __expf(s - mnew);
            const float* vrow = krow + DD;
            dsum = dsum * c + p;
            a0 = a0 * c + p * vrow[lane];
            a1 = a1 * c + p * vrow[lane + 32];
            m = mnew;
        }
    }

    float inv = 1.0f / dsum;
    float* orow = out + ((size_t)(b * LL + i)) * DD + h * DH;
    orow[lane]      = a0 * inv;
    orow[lane + 32] = a1 * inv;
}

// ---------------------------------------------------------------------------
// Launch
// ---------------------------------------------------------------------------
extern "C" void kernel_launch(void* const* d_in, const int* in_sizes, int n_in,
                              void* d_out, int out_size)
{
    const float* x     = (const float*)d_in[0];
    const float* in_w  = (const float*)d_in[1];
    const float* in_b  = (const float*)d_in[2];
    const float* out_w = (const float*)d_in[3];
    const float* out_b = (const float*)d_in[4];
    const float* ln1g  = (const float*)d_in[5];
    const float* ln1b  = (const float*)d_in[6];
    const float* ln2g  = (const float*)d_in[7];
    const float* ln2b  = (const float*)d_in[8];
    const float* w1    = (const float*)d_in[9];
    const float* b1    = (const float*)d_in[10];
    const float* w2    = (const float*)d_in[11];
    const float* b2    = (const float*)d_in[12];
    float* out = (float*)d_out;

    float *x2, *qkv, *attn, *xres, *hln, *ffn;
    cudaGetSymbolAddress((void**)&x2,   g_x2);
    cudaGetSymbolAddress((void**)&qkv,  g_qkv);
    cudaGetSymbolAddress((void**)&attn, g_attn);
    cudaGetSymbolAddress((void**)&xres, g_xres);
    cudaGetSymbolAddress((void**)&hln,  g_hln);
    cudaGetSymbolAddress((void**)&ffn,  g_ffn);

    int gy = (NROWS + 127) / 128;   // 65

    // 1. LN1
    ln_kernel<<<NROWS, 128>>>(x, ln1g, ln1b, x2);
    // 2. QKV = x2 @ in_w^T + in_b
    mma_gemm<0><<<dim3((3 * DD) / 128, gy), 256>>>(
        x2, in_w, in_b, nullptr, qkv, NROWS, 3 * DD, DD);
    // 3. attention
    attn_kernel<<<dim3(BB * HH, LL / 8), 256>>>(qkv, attn);
    // 4. xres = attn @ out_w^T + out_b + x
    mma_gemm<0><<<dim3(DD / 128, gy), 256>>>(
        attn, out_w, out_b, x, xres, NROWS, DD, DD);
    // 5. LN2
    ln_kernel<<<NROWS, 128>>>(xres, ln2g, ln2b, hln);
    // 6. ffn = gelu(hln @ w1^T + b1)
    mma_gemm<1><<<dim3(DFF / 128, gy), 256>>>(
        hln, w1, b1, nullptr, ffn, NROWS, DFF, DD);
    // 7. out = ffn @ w2^T + b2 + xres
    mma_gemm<0><<<dim3(DD / 128, gy), 256>>>(
        ffn, w2, b2, xres, out, NROWS, DD, DFF);
}

// round 4
// speedup vs baseline: 2.2488x; 1.1540x over previous
#include <cuda_runtime.h>
#include <cuda_bf16.h>
#include <math.h>

// Problem constants (fixed by the reference)
#define BB   4
#define TT   2048
#define MM   16
#define DD   512
#define HH   8
#define DFF  2048
#define WIN  128
#define LL   (MM + TT)          // 2064
#define NROWS (BB * LL)         // 8256
#define DH   64

// ---------------------------------------------------------------------------
// Scratch
// ---------------------------------------------------------------------------
__device__ float g_x2  [(size_t)NROWS * DD];
__device__ float g_qkv [(size_t)NROWS * 3 * DD];
__device__ float g_attn[(size_t)NROWS * DD];
__device__ float g_xres[(size_t)NROWS * DD];
__device__ float g_hln [(size_t)NROWS * DD];
__device__ float g_ffn [(size_t)NROWS * DFF];

// ---------------------------------------------------------------------------
// LayerNorm over D=512. One block (128 threads) per row.
// ---------------------------------------------------------------------------
__global__ void ln_kernel(const float* __restrict__ x,
                          const float* __restrict__ g,
                          const float* __restrict__ b,
                          float* __restrict__ y)
{
    int row = blockIdx.x;
    int t = threadIdx.x;
    const float4* xr = (const float4*)(x + (size_t)row * DD);
    float4 v = xr[t];
    float s  = v.x + v.y + v.z + v.w;
    float ss = v.x*v.x + v.y*v.y + v.z*v.z + v.w*v.w;

    int lane = t & 31, wid = t >> 5;
    #pragma unroll
    for (int o = 16; o > 0; o >>= 1) {
        s  += __shfl_xor_sync(0xffffffffu, s,  o);
        ss += __shfl_xor_sync(0xffffffffu, ss, o);
    }
    __shared__ float sh[8];
    if (lane == 0) { sh[wid] = s; sh[wid + 4] = ss; }
    __syncthreads();
    s  = sh[0] + sh[1] + sh[2] + sh[3];
    ss = sh[4] + sh[5] + sh[6] + sh[7];

    float mu  = s * (1.0f / DD);
    float var = ss * (1.0f / DD) - mu * mu;
    float inv = rsqrtf(var + 1e-5f);

    float4 gg = ((const float4*)g)[t];
    float4 bb = ((const float4*)b)[t];
    float4 o4;
    o4.x = (v.x - mu) * inv * gg.x + bb.x;
    o4.y = (v.y - mu) * inv * gg.y + bb.y;
    o4.z = (v.z - mu) * inv * gg.z + bb.z;
    o4.w = (v.w - mu) * inv * gg.w + bb.w;
    ((float4*)(y + (size_t)row * DD))[t] = o4;
}

// ---------------------------------------------------------------------------
// TF32 tensor-core GEMM (fast-tf32: raw fp32 bits, HW truncates to tf32).
// C[N,Mo] = A[N,K] @ W[Mo,K]^T + bias (+res) (+gelu)
// Block tile 128x128, BK=16, 256 threads (8 warps, 2x4, warp tile 64x32),
// mma.sync.m16n8k8, cp.async double-buffered smem (stride 20, conflict-free).
// ---------------------------------------------------------------------------
__device__ __forceinline__ void mma_tf32(float* c, const unsigned* a, const unsigned* b) {
    asm volatile(
        "mma.sync.aligned.m16n8k8.row.col.f32.tf32.tf32.f32 "
        "{%0,%1,%2,%3}, {%4,%5,%6,%7}, {%8,%9}, {%0,%1,%2,%3};"
        : "+f"(c[0]), "+f"(c[1]), "+f"(c[2]), "+f"(c[3])
        : "r"(a[0]), "r"(a[1]), "r"(a[2]), "r"(a[3]), "r"(b[0]), "r"(b[1]));
}

__device__ __forceinline__ void cp16(float* dst, const float* src, bool valid) {
    unsigned sa = (unsigned)__cvta_generic_to_shared(dst);
    int sz = valid ? 16 : 0;
    asm volatile("cp.async.cg.shared.global [%0], [%1], 16, %2;\n"
                 :: "r"(sa), "l"(src), "r"(sz));
}
#define CP_COMMIT() asm volatile("cp.async.commit_group;\n" ::: "memory")
#define CP_WAIT1()  asm volatile("cp.async.wait_group 1;\n" ::: "memory")

template<int ACT>
__global__ __launch_bounds__(256) void mma_gemm(
    const float* __restrict__ A,
    const float* __restrict__ W,
    const float* __restrict__ bias,
    const float* __restrict__ res,
    float* __restrict__ C,
    int N, int Mo, int K)
{
    __shared__ __align__(16) float As[2][128][20];
    __shared__ __align__(16) float Ws[2][128][20];

    int tid  = threadIdx.x;
    int lane = tid & 31;
    int wid  = tid >> 5;
    int wm   = wid >> 2;          // 0..1
    int wn   = wid & 3;           // 0..3
    int n0   = blockIdx.y * 128;
    int m0   = blockIdx.x * 128;

    int lr = tid >> 2;            // 0..63
    int lc = (tid & 3) * 4;       // 0,4,8,12

    const float* Ap0 = A + (size_t)(n0 + lr)      * K + lc;
    const float* Ap1 = A + (size_t)(n0 + lr + 64) * K + lc;
    const float* Wp0 = W + (size_t)(m0 + lr)      * K + lc;
    const float* Wp1 = W + (size_t)(m0 + lr + 64) * K + lc;
    bool v0 = (n0 + lr)      < N;
    bool v1 = (n0 + lr + 64) < N;

    float acc[4][4][4];
    #pragma unroll
    for (int i = 0; i < 4; i++)
        #pragma unroll
        for (int j = 0; j < 4; j++)
            #pragma unroll
            for (int q = 0; q < 4; q++) acc[i][j][q] = 0.0f;

    int nIter = K >> 4;
    int lq = lane >> 2;      // 0..7
    int lk = lane & 3;       // 0..3

    // prologue: stage 0
    cp16(&As[0][lr][lc],      Ap0, v0);
    cp16(&As[0][lr + 64][lc], Ap1, v1);
    cp16(&Ws[0][lr][lc],      Wp0, true);
    cp16(&Ws[0][lr + 64][lc], Wp1, true);
    CP_COMMIT();

    for (int it = 0; it < nIter; it++) {
        if (it + 1 < nIter) {
            int k0 = (it + 1) << 4;
            int nb = (it + 1) & 1;
            cp16(&As[nb][lr][lc],      Ap0 + k0, v0);
            cp16(&As[nb][lr + 64][lc], Ap1 + k0, v1);
            cp16(&Ws[nb][lr][lc],      Wp0 + k0, true);
            cp16(&Ws[nb][lr + 64][lc], Wp1 + k0, true);
        }
        CP_COMMIT();
        CP_WAIT1();
        __syncthreads();

        int buf = it & 1;
        #pragma unroll
        for (int ks = 0; ks < 2; ks++) {
            int kb = ks * 8;
            unsigned af[4][4];
            unsigned bf[4][2];
            #pragma unroll
            for (int am = 0; am < 4; am++) {
                int mr = wm * 64 + am * 16 + lq;
                af[am][0] = __float_as_uint(As[buf][mr][kb + lk]);
                af[am][1] = __float_as_uint(As[buf][mr + 8][kb + lk]);
                af[am][2] = __float_as_uint(As[buf][mr][kb + lk + 4]);
                af[am][3] = __float_as_uint(As[buf][mr + 8][kb + lk + 4]);
            }
            #pragma unroll
            for (int an = 0; an < 4; an++) {
                int nr = wn * 32 + an * 8 + lq;
                bf[an][0] = __float_as_uint(Ws[buf][nr][kb + lk]);
                bf[an][1] = __float_as_uint(Ws[buf][nr][kb + lk + 4]);
            }
            #pragma unroll
            for (int am = 0; am < 4; am++)
                #pragma unroll
                for (int an = 0; an < 4; an++)
                    mma_tf32(acc[am][an], af[am], bf[an]);
        }
        __syncthreads();
    }

    // epilogue
    #pragma unroll
    for (int am = 0; am < 4; am++) {
        #pragma unroll
        for (int an = 0; an < 4; an++) {
            int r0 = n0 + wm * 64 + am * 16 + lq;
            int c0 = m0 + wn * 32 + an * 8 + lk * 2;
            float b0 = bias[c0], b1 = bias[c0 + 1];
            #pragma unroll
            for (int half = 0; half < 2; half++) {
                int row = r0 + half * 8;
                if (row < N) {
                    float u0 = acc[am][an][half * 2 + 0] + b0;
                    float u1 = acc[am][an][half * 2 + 1] + b1;
                    if (ACT == 1) {
                        u0 = 0.5f * u0 * (1.0f + erff(u0 * 0.70710678118654752f));
                        u1 = 0.5f * u1 * (1.0f + erff(u1 * 0.70710678118654752f));
                    }
                    if (res) {
                        const float2 rr = *(const float2*)(res + (size_t)row * Mo + c0);
                        u0 += rr.x; u1 += rr.y;
                    }
                    *(float2*)(C + (size_t)row * Mo + c0) = make_float2(u0, u1);
                }
            }
        }
    }
}

// ---------------------------------------------------------------------------
// Banded attention. One warp per (b,h,query). Online softmax, 2 keys/iter,
// float2 accesses.
// ---------------------------------------------------------------------------
__global__ void attn_kernel(const float* __restrict__ qkv,
                            float* __restrict__ out)
{
    int lane = threadIdx.x & 31;
    int wid  = threadIdx.x >> 5;
    int bh = blockIdx.x;
    int b = bh >> 3;
    int h = bh & 7;
    int i = blockIdx.y * 8 + wid;
    if (i >= LL) return;

    const float* base = qkv + (size_t)b * LL * (3 * DD);
    float2 q = *(const float2*)(base + (size_t)i * (3 * DD) + h * DH + 2 * lane);

    float m = -1e30f, dsum = 0.0f;
    float2 a = make_float2(0.f, 0.f);
    const float scale = 0.125f;           // 1/sqrt(64)

    int rA_lo, rA_hi, rB_lo, rB_hi;       // inclusive
    if (i < MM) {
        rA_lo = 0; rA_hi = i;
        rB_lo = 1; rB_hi = 0;             // empty
    } else {
        rA_lo = 0; rA_hi = MM - 1;
        rB_lo = (i - WIN + 1 > MM) ? (i - WIN + 1) : MM;
        rB_hi = i;
    }

    for (int r = 0; r < 2; r++) {
        int lo = (r == 0) ? rA_lo : rB_lo;
        int hi = (r == 0) ? rA_hi : rB_hi;
        int j = lo;
        // pairs
        for (; j + 1 <= hi; j += 2) {
            const float* k0p = base + (size_t)j * (3 * DD) + DD + h * DH;
            const float* k1p = k0p + 3 * DD;
            float2 k0 = *(const float2*)(k0p + 2 * lane);
            float2 k1 = *(const float2*)(k1p + 2 * lane);
            float s0 = q.x * k0.x + q.y * k0.y;
            float s1 = q.x * k1.x + q.y * k1.y;
            #pragma unroll
            for (int o = 16; o > 0; o >>= 1) {
                s0 += __shfl_xor_sync(0xffffffffu, s0, o);
                s1 += __shfl_xor_sync(0xffffffffu, s1, o);
            }
            s0 *= scale; s1 *= scale;
            float mnew = fmaxf(m, fmaxf(s0, s1));
            float c  = __expf(m - mnew);
            float p0 = __expf(s0 - mnew);
            float p1 = __expf(s1 - mnew);
            float2 v0 = *(const float2*)(k0p + DD + 2 * lane);
            float2 v1 = *(const float2*)(k1p + DD + 2 * lane);
            dsum = dsum * c + p0 + p1;
            a.x = a.x * c + p0 * v0.x + p1 * v1.x;
            a.y = a.y * c + p0 * v0.y + p1 * v1.y;
            m = mnew;
        }
        // tail
        if (j == hi) {
            const float* k0p = base + (size_t)j * (3 * DD) + DD + h * DH;
            float2 k0 = *(const float2*)(k0p + 2 * lane);
            float s0 = q.x * k0.x + q.y * k0.y;
            #pragma unroll
            for (int o = 16; o > 0; o >>= 1)
                s0 += __shfl_xor_sync(0xffffffffu, s0, o);
            s0 *= scale;
            float mnew = fmaxf(m, s0);
            float c  = __expf(m - mnew);
            float p0 = __expf(s0 - mnew);
            float2 v0 = *(const float2*)(k0p + DD + 2 * lane);
            dsum = dsum * c + p0;
            a.x = a.x * c + p0 * v0.x;
            a.y = a.y * c + p0 * v0.y;
            m = mnew;
        }
    }

    float inv = 1.0f / dsum;
    float* orow = out + ((size_t)(b * LL + i)) * DD + h * DH;
    *(float2*)(orow + 2 * lane) = make_float2(a.x * inv, a.y * inv);
}

// ---------------------------------------------------------------------------
// Launch
// ---------------------------------------------------------------------------
extern "C" void kernel_launch(void* const* d_in, const int* in_sizes, int n_in,
                              void* d_out, int out_size)
{
    const float* x     = (const float*)d_in[0];
    const float* in_w  = (const float*)d_in[1];
    const float* in_b  = (const float*)d_in[2];
    const float* out_w = (const float*)d_in[3];
    const float* out_b = (const float*)d_in[4];
    const float* ln1g  = (const float*)d_in[5];
    const float* ln1b  = (const float*)d_in[6];
    const float* ln2g  = (const float*)d_in[7];
    const float* ln2b  = (const float*)d_in[8];
    const float* w1    = (const float*)d_in[9];
    const float* b1    = (const float*)d_in[10];
    const float* w2    = (const float*)d_in[11];
    const float* b2    = (const float*)d_in[12];
    float* out = (float*)d_out;

    float *x2, *qkv, *attn, *xres, *hln, *ffn;
    cudaGetSymbolAddress((void**)&x2,   g_x2);
    cudaGetSymbolAddress((void**)&qkv,  g_qkv);
    cudaGetSymbolAddress((void**)&attn, g_attn);
    cudaGetSymbolAddress((void**)&xres, g_xres);
    cudaGetSymbolAddress((void**)&hln,  g_hln);
    cudaGetSymbolAddress((void**)&ffn,  g_ffn);

    int gy = (NROWS + 127) / 128;   // 65

    // 1. LN1
    ln_kernel<<<NROWS, 128>>>(x, ln1g, ln1b, x2);
    // 2. QKV = x2 @ in_w^T + in_b
    mma_gemm<0><<<dim3((3 * DD) / 128, gy), 256>>>(
        x2, in_w, in_b, nullptr, qkv, NROWS, 3 * DD, DD);
    // 3. attention
    attn_kernel<<<dim3(BB * HH, LL / 8), 256>>>(qkv, attn);
    // 4. xres = attn @ out_w^T + out_b + x
    mma_gemm<0><<<dim3(DD / 128, gy), 256>>>(
        attn, out_w, out_b, x, xres, NROWS, DD, DD);
    // 5. LN2
    ln_kernel<<<NROWS, 128>>>(xres, ln2g, ln2b, hln);
    // 6. ffn = gelu(hln @ w1^T + b1)
    mma_gemm<1><<<dim3(DFF / 128, gy), 256>>>(
        hln, w1, b1, nullptr, ffn, NROWS, DFF, DD);
    // 7. out = ffn @ w2^T + b2 + xres
    mma_gemm<0><<<dim3(DD / 128, gy), 256>>>(
        ffn, w2, b2, xres, out, NROWS, DD, DFF);
}

// round 5
// speedup vs baseline: 2.2746x; 1.0115x over previous
#include <cuda_runtime.h>
#include <cuda_bf16.h>
#include <math.h>

// Problem constants (fixed by the reference)
#define BB   4
#define TT   2048
#define MM   16
#define DD   512
#define HH   8
#define DFF  2048
#define WIN  128
#define LL   (MM + TT)          // 2064
#define NROWS (BB * LL)         // 8256
#define DH   64

// ---------------------------------------------------------------------------
// Scratch
// ---------------------------------------------------------------------------
__device__ float g_x2  [(size_t)NROWS * DD];
__device__ float g_qkv [(size_t)NROWS * 3 * DD];
__device__ float g_attn[(size_t)NROWS * DD];
__device__ float g_xres[(size_t)NROWS * DD];
__device__ float g_hln [(size_t)NROWS * DD];
__device__ float g_ffn [(size_t)NROWS * DFF];

// ---------------------------------------------------------------------------
// LayerNorm over D=512. One block (128 threads) per row.
// ---------------------------------------------------------------------------
__global__ void ln_kernel(const float* __restrict__ x,
                          const float* __restrict__ g,
                          const float* __restrict__ b,
                          float* __restrict__ y)
{
    int row = blockIdx.x;
    int t = threadIdx.x;
    const float4* xr = (const float4*)(x + (size_t)row * DD);
    float4 v = xr[t];
    float s  = v.x + v.y + v.z + v.w;
    float ss = v.x*v.x + v.y*v.y + v.z*v.z + v.w*v.w;

    int lane = t & 31, wid = t >> 5;
    #pragma unroll
    for (int o = 16; o > 0; o >>= 1) {
        s  += __shfl_xor_sync(0xffffffffu, s,  o);
        ss += __shfl_xor_sync(0xffffffffu, ss, o);
    }
    __shared__ float sh[8];
    if (lane == 0) { sh[wid] = s; sh[wid + 4] = ss; }
    __syncthreads();
    s  = sh[0] + sh[1] + sh[2] + sh[3];
    ss = sh[4] + sh[5] + sh[6] + sh[7];

    float mu  = s * (1.0f / DD);
    float var = ss * (1.0f / DD) - mu * mu;
    float inv = rsqrtf(var + 1e-5f);

    float4 gg = ((const float4*)g)[t];
    float4 bb = ((const float4*)b)[t];
    float4 o4;
    o4.x = (v.x - mu) * inv * gg.x + bb.x;
    o4.y = (v.y - mu) * inv * gg.y + bb.y;
    o4.z = (v.z - mu) * inv * gg.z + bb.z;
    o4.w = (v.w - mu) * inv * gg.w + bb.w;
    ((float4*)(y + (size_t)row * DD))[t] = o4;
}

// ---------------------------------------------------------------------------
// TF32 tensor-core GEMM (fast-tf32: raw fp32 bits, HW truncates to tf32).
// C[N,Mo] = A[N,K] @ W[Mo,K]^T + bias (+res) (+gelu)
// Block tile 128x128, BK=16, 256 threads (8 warps, 2x4, warp tile 64x32),
// mma.sync.m16n8k8, 4-stage cp.async ring in dynamic smem (stride 20),
// single __syncthreads per k-iteration.
// ---------------------------------------------------------------------------
#define STAGES 4
#define STAGE_FLOATS (2 * 128 * 20)     // A half + W half
#define W_OFF (128 * 20)
#define GEMM_SMEM_BYTES (STAGES * STAGE_FLOATS * 4)   // 81920

__device__ __forceinline__ void mma_tf32(float* c, const unsigned* a, const unsigned* b) {
    asm volatile(
        "mma.sync.aligned.m16n8k8.row.col.f32.tf32.tf32.f32 "
        "{%0,%1,%2,%3}, {%4,%5,%6,%7}, {%8,%9}, {%0,%1,%2,%3};"
        : "+f"(c[0]), "+f"(c[1]), "+f"(c[2]), "+f"(c[3])
        : "r"(a[0]), "r"(a[1]), "r"(a[2]), "r"(a[3]), "r"(b[0]), "r"(b[1]));
}

__device__ __forceinline__ void cp16(float* dst, const float* src, bool valid) {
    unsigned sa = (unsigned)__cvta_generic_to_shared(dst);
    int sz = valid ? 16 : 0;
    asm volatile("cp.async.cg.shared.global [%0], [%1], 16, %2;\n"
                 :: "r"(sa), "l"(src), "r"(sz));
}
#define CP_COMMIT() asm volatile("cp.async.commit_group;\n" ::: "memory")

template<int ACT>
__global__ __launch_bounds__(256) void mma_gemm(
    const float* __restrict__ A,
    const float* __restrict__ W,
    const float* __restrict__ bias,
    const float* __restrict__ res,
    float* __restrict__ C,
    int N, int Mo, int K)
{
    extern __shared__ float smem[];

    int tid  = threadIdx.x;
    int lane = tid & 31;
    int wid  = tid >> 5;
    int wm   = wid >> 2;          // 0..1
    int wn   = wid & 3;           // 0..3
    int n0   = blockIdx.y * 128;
    int m0   = blockIdx.x * 128;

    int lr = tid >> 2;            // 0..63
    int lc = (tid & 3) * 4;       // 0,4,8,12

    const float* Ap0 = A + (size_t)(n0 + lr)      * K + lc;
    const float* Ap1 = A + (size_t)(n0 + lr + 64) * K + lc;
    const float* Wp0 = W + (size_t)(m0 + lr)      * K + lc;
    const float* Wp1 = W + (size_t)(m0 + lr + 64) * K + lc;
    bool v0 = (n0 + lr)      < N;
    bool v1 = (n0 + lr + 64) < N;

    float acc[4][4][4];
    #pragma unroll
    for (int i = 0; i < 4; i++)
        #pragma unroll
        for (int j = 0; j < 4; j++)
            #pragma unroll
            for (int q = 0; q < 4; q++) acc[i][j][q] = 0.0f;

    int nIter = K >> 4;
    int lq = lane >> 2;      // 0..7
    int lk = lane & 3;       // 0..3

    // prologue: issue STAGES-1 stages
    #pragma unroll
    for (int s = 0; s < STAGES - 1; s++) {
        if (s < nIter) {
            float* sb = smem + s * STAGE_FLOATS;
            int k0 = s << 4;
            cp16(sb + lr * 20 + lc,                Ap0 + k0, v0);
            cp16(sb + (lr + 64) * 20 + lc,         Ap1 + k0, v1);
            cp16(sb + W_OFF + lr * 20 + lc,        Wp0 + k0, true);
            cp16(sb + W_OFF + (lr + 64) * 20 + lc, Wp1 + k0, true);
        }
        CP_COMMIT();
    }

    for (int it = 0; it < nIter; it++) {
        asm volatile("cp.async.wait_group %0;\n" :: "n"(STAGES - 2));
        __syncthreads();

        // issue load for iteration it+STAGES-1 (overwrites slot computed at it-1)
        int nx = it + STAGES - 1;
        if (nx < nIter) {
            float* sb = smem + (nx & (STAGES - 1)) * STAGE_FLOATS;
            int k0 = nx << 4;
            cp16(sb + lr * 20 + lc,                Ap0 + k0, v0);
            cp16(sb + (lr + 64) * 20 + lc,         Ap1 + k0, v1);
            cp16(sb + W_OFF + lr * 20 + lc,        Wp0 + k0, true);
            cp16(sb + W_OFF + (lr + 64) * 20 + lc, Wp1 + k0, true);
        }
        CP_COMMIT();

        const float* sa = smem + (it & (STAGES - 1)) * STAGE_FLOATS;
        const float* sw = sa + W_OFF;

        #pragma unroll
        for (int ks = 0; ks < 2; ks++) {
            int kb = ks * 8;
            unsigned af[4][4];
            unsigned bf[4][2];
            #pragma unroll
            for (int am = 0; am < 4; am++) {
                int mr = wm * 64 + am * 16 + lq;
                af[am][0] = __float_as_uint(sa[mr * 20 + kb + lk]);
                af[am][1] = __float_as_uint(sa[(mr + 8) * 20 + kb + lk]);
                af[am][2] = __float_as_uint(sa[mr * 20 + kb + lk + 4]);
                af[am][3] = __float_as_uint(sa[(mr + 8) * 20 + kb + lk + 4]);
            }
            #pragma unroll
            for (int an = 0; an < 4; an++) {
                int nr = wn * 32 + an * 8 + lq;
                bf[an][0] = __float_as_uint(sw[nr * 20 + kb + lk]);
                bf[an][1] = __float_as_uint(sw[nr * 20 + kb + lk + 4]);
            }
            #pragma unroll
            for (int am = 0; am < 4; am++)
                #pragma unroll
                for (int an = 0; an < 4; an++)
                    mma_tf32(acc[am][an], af[am], bf[an]);
        }
    }

    // epilogue
    #pragma unroll
    for (int am = 0; am < 4; am++) {
        #pragma unroll
        for (int an = 0; an < 4; an++) {
            int r0 = n0 + wm * 64 + am * 16 + lq;
            int c0 = m0 + wn * 32 + an * 8 + lk * 2;
            float b0 = bias[c0], b1 = bias[c0 + 1];
            #pragma unroll
            for (int half = 0; half < 2; half++) {
                int row = r0 + half * 8;
                if (row < N) {
                    float u0 = acc[am][an][half * 2 + 0] + b0;
                    float u1 = acc[am][an][half * 2 + 1] + b1;
                    if (ACT == 1) {
                        u0 = 0.5f * u0 * (1.0f + erff(u0 * 0.70710678118654752f));
                        u1 = 0.5f * u1 * (1.0f + erff(u1 * 0.70710678118654752f));
                    }
                    if (res) {
                        const float2 rr = *(const float2*)(res + (size_t)row * Mo + c0);
                        u0 += rr.x; u1 += rr.y;
                    }
                    *(float2*)(C + (size_t)row * Mo + c0) = make_float2(u0, u1);
                }
            }
        }
    }
}

// ---------------------------------------------------------------------------
// Banded attention. One warp per (b,h,query). Online softmax, 4 keys/iter,
// float2 accesses.
// ---------------------------------------------------------------------------
__global__ void attn_kernel(const float* __restrict__ qkv,
                            float* __restrict__ out)
{
    int lane = threadIdx.x & 31;
    int wid  = threadIdx.x >> 5;
    int bh = blockIdx.x;
    int b = bh >> 3;
    int h = bh & 7;
    int i = blockIdx.y * 8 + wid;
    if (i >= LL) return;

    const float* base = qkv + (size_t)b * LL * (3 * DD);
    float2 q = *(const float2*)(base + (size_t)i * (3 * DD) + h * DH + 2 * lane);

    float m = -1e30f, dsum = 0.0f;
    float2 a = make_float2(0.f, 0.f);
    const float scale = 0.125f;           // 1/sqrt(64)

    int rA_lo, rA_hi, rB_lo, rB_hi;       // inclusive
    if (i < MM) {
        rA_lo = 0; rA_hi = i;
        rB_lo = 1; rB_hi = 0;             // empty
    } else {
        rA_lo = 0; rA_hi = MM - 1;
        rB_lo = (i - WIN + 1 > MM) ? (i - WIN + 1) : MM;
        rB_hi = i;
    }

    const int kstride = 3 * DD;
    for (int r = 0; r < 2; r++) {
        int lo = (r == 0) ? rA_lo : rB_lo;
        int hi = (r == 0) ? rA_hi : rB_hi;
        int j = lo;
        // quads
        for (; j + 3 <= hi; j += 4) {
            const float* kp = base + (size_t)j * kstride + DD + h * DH + 2 * lane;
            float2 k0 = *(const float2*)(kp);
            float2 k1 = *(const float2*)(kp + kstride);
            float2 k2 = *(const float2*)(kp + 2 * kstride);
            float2 k3 = *(const float2*)(kp + 3 * kstride);
            float s0 = q.x * k0.x + q.y * k0.y;
            float s1 = q.x * k1.x + q.y * k1.y;
            float s2 = q.x * k2.x + q.y * k2.y;
            float s3 = q.x * k3.x + q.y * k3.y;
            #pragma unroll
            for (int o = 16; o > 0; o >>= 1) {
                s0 += __shfl_xor_sync(0xffffffffu, s0, o);
                s1 += __shfl_xor_sync(0xffffffffu, s1, o);
                s2 += __shfl_xor_sync(0xffffffffu, s2, o);
                s3 += __shfl_xor_sync(0xffffffffu, s3, o);
            }
            s0 *= scale; s1 *= scale; s2 *= scale; s3 *= scale;
            float mnew = fmaxf(fmaxf(m, fmaxf(s0, s1)), fmaxf(s2, s3));
            float c  = __expf(m - mnew);
            float p0 = __expf(s0 - mnew);
            float p1 = __expf(s1 - mnew);
            float p2 = __expf(s2 - mnew);
            float p3 = __expf(s3 - mnew);
            const float* vp = kp + DD;
            float2 v0 = *(const float2*)(vp);
            float2 v1 = *(const float2*)(vp + kstride);
            float2 v2 = *(const float2*)(vp + 2 * kstride);
            float2 v3 = *(const float2*)(vp + 3 * kstride);
            dsum = dsum * c + (p0 + p1) + (p2 + p3);
            a.x = a.x * c + p0 * v0.x + p1 * v1.x + p2 * v2.x + p3 * v3.x;
            a.y = a.y * c + p0 * v0.y + p1 * v1.y + p2 * v2.y + p3 * v3.y;
            m = mnew;
        }
        // tail singles
        for (; j <= hi; j++) {
            const float* kp = base + (size_t)j * kstride + DD + h * DH + 2 * lane;
            float2 k0 = *(const float2*)(kp);
            float s0 = q.x * k0.x + q.y * k0.y;
            #pragma unroll
            for (int o = 16; o > 0; o >>= 1)
                s0 += __shfl_xor_sync(0xffffffffu, s0, o);
            s0 *= scale;
            float mnew = fmaxf(m, s0);
            float c  = __expf(m - mnew);
            float p0 = __expf(s0 - mnew);
            float2 v0 = *(const float2*)(kp + DD);
            dsum = dsum * c + p0;
            a.x = a.x * c + p0 * v0.x;
            a.y = a.y * c + p0 * v0.y;
            m = mnew;
        }
    }

    float inv = 1.0f / dsum;
    float* orow = out + ((size_t)(b * LL + i)) * DD + h * DH;
    *(float2*)(orow + 2 * lane) = make_float2(a.x * inv, a.y * inv);
}

// ---------------------------------------------------------------------------
// Launch
// ---------------------------------------------------------------------------
extern "C" void kernel_launch(void* const* d_in, const int* in_sizes, int n_in,
                              void* d_out, int out_size)
{
    const float* x     = (const float*)d_in[0];
    const float* in_w  = (const float*)d_in[1];
    const float* in_b  = (const float*)d_in[2];
    const float* out_w = (const float*)d_in[3];
    const float* out_b = (const float*)d_in[4];
    const float* ln1g  = (const float*)d_in[5];
    const float* ln1b  = (const float*)d_in[6];
    const float* ln2g  = (const float*)d_in[7];
    const float* ln2b  = (const float*)d_in[8];
    const float* w1    = (const float*)d_in[9];
    const float* b1    = (const float*)d_in[10];
    const float* w2    = (const float*)d_in[11];
    const float* b2    = (const float*)d_in[12];
    float* out = (float*)d_out;

    float *x2, *qkv, *attn, *xres, *hln, *ffn;
    cudaGetSymbolAddress((void**)&x2,   g_x2);
    cudaGetSymbolAddress((void**)&qkv,  g_qkv);
    cudaGetSymbolAddress((void**)&attn, g_attn);
    cudaGetSymbolAddress((void**)&xres, g_xres);
    cudaGetSymbolAddress((void**)&hln,  g_hln);
    cudaGetSymbolAddress((void**)&ffn,  g_ffn);

    cudaFuncSetAttribute(mma_gemm<0>, cudaFuncAttributeMaxDynamicSharedMemorySize, GEMM_SMEM_BYTES);
    cudaFuncSetAttribute(mma_gemm<1>, cudaFuncAttributeMaxDynamicSharedMemorySize, GEMM_SMEM_BYTES);

    int gy = (NROWS + 127) / 128;   // 65

    // 1. LN1
    ln_kernel<<<NROWS, 128>>>(x, ln1g, ln1b, x2);
    // 2. QKV = x2 @ in_w^T + in_b
    mma_gemm<0><<<dim3((3 * DD) / 128, gy), 256, GEMM_SMEM_BYTES>>>(
        x2, in_w, in_b, nullptr, qkv, NROWS, 3 * DD, DD);
    // 3. attention
    attn_kernel<<<dim3(BB * HH, LL / 8), 256>>>(qkv, attn);
    // 4. xres = attn @ out_w^T + out_b + x
    mma_gemm<0><<<dim3(DD / 128, gy), 256, GEMM_SMEM_BYTES>>>(
        attn, out_w, out_b, x, xres, NROWS, DD, DD);
    // 5. LN2
    ln_kernel<<<NROWS, 128>>>(xres, ln2g, ln2b, hln);
    // 6. ffn = gelu(hln @ w1^T + b1)
    mma_gemm<1><<<dim3(DFF / 128, gy), 256, GEMM_SMEM_BYTES>>>(
        hln, w1, b1, nullptr, ffn, NROWS, DFF, DD);
    // 7. out = ffn @ w2^T + b2 + xres
    mma_gemm<0><<<dim3(DD / 128, gy), 256, GEMM_SMEM_BYTES>>>(
        ffn, w2, b2, xres, out, NROWS, DD, DFF);
}